// round 12
// baseline (speedup 1.0000x reference)
#include <cuda_runtime.h>
#include <cuda_fp16.h>
#include <cuda_fp8.h>
#include <cstdint>
#include <cstddef>

// ---------------------------------------------------------------------------
// Problem constants
// ---------------------------------------------------------------------------
#define MTOK   4096
#define DIM    1024
#define TDIM   3072
#define HEADS  16
#define HD     64
#define HIDDEN 2730
#define HPAD   2816
#define NSEQ   1024
#define QSCALE 0.125f
#define LN_EPS 1e-6f
#define PSCALE 256.f
#define INV_PSCALE (1.f / 256.f)
#define WSCALE 16.f
#define WSINV  (1.f / 16.f)

typedef __half hf;
typedef unsigned char f8;

// ---------------------------------------------------------------------------
// Scratch (device globals)
// ---------------------------------------------------------------------------
__device__ f8    g_h   [MTOK * DIM];
__device__ hf    g_qkv [MTOK * TDIM];
__device__ hf    g_qi  [4 * HEADS * NSEQ * HD];
__device__ f8    g_attn[(size_t)4 * HEADS * NSEQ * NSEQ];
__device__ f8    g_vt  [(size_t)4 * HEADS * HD * NSEQ];
__device__ f8    g_o   [MTOK * DIM];
__device__ float g_x1  [MTOK * DIM];
__device__ f8    g_h2  [MTOK * DIM];
__device__ f8    g_act [MTOK * HPAD];
// transposed fp8 weights (x16 scaled): [N][K] layouts
__device__ f8    g_wqT[TDIM * DIM];    // [3072][1024]
__device__ f8    g_wpT[DIM * DIM];     // [1024][1024]
__device__ f8    g_wwT[HPAD * DIM];    // [2816][1024], n-pad zero
__device__ f8    g_wgT[HPAD * DIM];    // [2816][1024]
__device__ f8    g_woT[DIM * HPAD];    // [1024][2816], k-pad zero

// ---------------------------------------------------------------------------
// PTX helpers
// ---------------------------------------------------------------------------
__device__ __forceinline__ uint32_t smem_u32(const void* p) {
    uint32_t a;
    asm("{ .reg .u64 t; cvta.to.shared.u64 t, %1; cvt.u32.u64 %0, t; }" : "=r"(a) : "l"(p));
    return a;
}
__device__ __forceinline__ void cp_async16(uint32_t dst, const void* src) {
    asm volatile("cp.async.cg.shared.global [%0], [%1], 16;" :: "r"(dst), "l"(src));
}
__device__ __forceinline__ void cp_commit() { asm volatile("cp.async.commit_group;"); }
template <int N> __device__ __forceinline__ void cp_wait() {
    asm volatile("cp.async.wait_group %0;" :: "n"(N));
}
__device__ __forceinline__ void ldm_x4(uint32_t* r, uint32_t a) {
    asm volatile("ldmatrix.sync.aligned.m8n8.x4.shared.b16 {%0,%1,%2,%3}, [%4];"
                 : "=r"(r[0]), "=r"(r[1]), "=r"(r[2]), "=r"(r[3]) : "r"(a));
}
__device__ __forceinline__ void ldm_x4_t(uint32_t* r, uint32_t a) {
    asm volatile("ldmatrix.sync.aligned.m8n8.x4.trans.shared.b16 {%0,%1,%2,%3}, [%4];"
                 : "=r"(r[0]), "=r"(r[1]), "=r"(r[2]), "=r"(r[3]) : "r"(a));
}
__device__ __forceinline__ void mma_f16(uint32_t* d, const uint32_t* a, const uint32_t* b) {
    asm volatile(
        "mma.sync.aligned.m16n8k16.row.col.f16.f16.f16.f16 "
        "{%0,%1},{%2,%3,%4,%5},{%6,%7},{%0,%1};"
        : "+r"(d[0]), "+r"(d[1])
        : "r"(a[0]), "r"(a[1]), "r"(a[2]), "r"(a[3]), "r"(b[0]), "r"(b[1]));
}
// fp8 e4m3 MMA, f32 accumulate
__device__ __forceinline__ void mma_e4(float* d, const uint32_t* a, const uint32_t* b) {
    asm volatile(
        "mma.sync.aligned.m16n8k32.row.col.f32.e4m3.e4m3.f32 "
        "{%0,%1,%2,%3},{%4,%5,%6,%7},{%8,%9},{%0,%1,%2,%3};"
        : "+f"(d[0]), "+f"(d[1]), "+f"(d[2]), "+f"(d[3])
        : "r"(a[0]), "r"(a[1]), "r"(a[2]), "r"(a[3]), "r"(b[0]), "r"(b[1]));
}
__device__ __forceinline__ float2 h2f2(uint32_t u) {
    __half2 h = *reinterpret_cast<__half2*>(&u);
    return __half22float2(h);
}
__device__ __forceinline__ unsigned short f2tofp8(float2 v) {
    return __nv_cvt_float2_to_fp8x2(v, __NV_SATFINITE, __NV_E4M3);
}
__device__ __forceinline__ __half2 fp8toh2(unsigned short raw) {
    __half2_raw hr = __nv_cvt_fp8x2_to_halfraw2(raw, __NV_E4M3);
    return *reinterpret_cast<__half2*>(&hr);
}
__device__ __forceinline__ unsigned short h2tofp8(__half2 v) {
    __half2_raw hr = *reinterpret_cast<__half2_raw*>(&v);
    return __nv_cvt_halfraw2_to_fp8x2(hr, __NV_SATFINITE, __NV_E4M3);
}

// ---------------------------------------------------------------------------
// Transpose + convert weight: src fp32 [R][C] -> dst fp8 [CP][RP] * WSCALE
//   64x64 tiles; RP, CP multiples of 64.
// ---------------------------------------------------------------------------
__global__ void __launch_bounds__(256)
convw_t(const float* __restrict__ src, f8* __restrict__ dst,
        int R, int C, int RP, int CP) {
    __shared__ float s[64][65];
    const int r0 = blockIdx.x * 64, c0 = blockIdx.y * 64;
    const int t = threadIdx.x;
#pragma unroll
    for (int i = 0; i < 16; i++) {
        int idx = t + 256 * i, rr = idx >> 6, cc = idx & 63;
        float v = 0.f;
        if (r0 + rr < R && c0 + cc < C)
            v = src[(size_t)(r0 + rr) * C + c0 + cc] * WSCALE;
        s[rr][cc] = v;
    }
    __syncthreads();
#pragma unroll
    for (int i = 0; i < 16; i++) {
        int idx = t + 256 * i, cc = idx >> 6, rr = idx & 63;
        dst[(size_t)(c0 + cc) * RP + r0 + rr] =
            (f8)__nv_cvt_float_to_fp8(s[rr][cc], __NV_SATFINITE, __NV_E4M3);
    }
}

// ---------------------------------------------------------------------------
// fp8 MMA GEMM, 4-stage cp.async, 2 CTAs/SM: C[M,N] = epi(A[M,K] @ BT^T)
//   A fp8 [M][K], BT fp8 [N][K] (pre-transposed weights, x16)
//   128x128 CTA, 4 warps (2x2), warp 64x64, K-chunk 64 bytes
// ---------------------------------------------------------------------------
#define G8P 80
#define G8STG 4
#define GEMM8_SMEM (G8STG * (128 * G8P + 128 * G8P))   // 81920 B

template <bool RES, bool OHF>
__global__ void __launch_bounds__(128, 2)
gemm_f8(const f8* __restrict__ A, const f8* __restrict__ BT, void* __restrict__ Cv,
        int K, int N, const float* __restrict__ bias,
        const float* __restrict__ res, const float* __restrict__ scale) {
    extern __shared__ f8 smp8[];
    const uint32_t sA0 = smem_u32(smp8);
    const uint32_t sB0 = sA0 + G8STG * 128 * G8P;
    const int tid = threadIdx.x, lane = tid & 31, wid = tid >> 5;
    const int wm = wid & 1, wn = wid >> 1;
    const int row0 = blockIdx.y * 128, col0 = blockIdx.x * 128;
    const int NC = K >> 6;

    auto pf = [&](int c, int buf) {
        int k0 = c << 6;
        uint32_t aD = sA0 + (uint32_t)buf * 128 * G8P;
        uint32_t bD = sB0 + (uint32_t)buf * 128 * G8P;
#pragma unroll
        for (int i = 0; i < 4; i++) {
            int idx = tid + 128 * i, r = idx >> 2, q = idx & 3;
            cp_async16(aD + (uint32_t)(r * G8P + q * 16),
                       A + (size_t)(row0 + r) * K + k0 + q * 16);
            cp_async16(bD + (uint32_t)(r * G8P + q * 16),
                       BT + (size_t)(col0 + r) * K + k0 + q * 16);
        }
        cp_commit();
    };

    const int a_r = wm * 64 + (lane & 7) + ((lane & 8) ? 8 : 0);
    const int a_cB = (lane & 16) ? 16 : 0;
    const int b_r = wn * 64 + (lane & 7) + ((lane & 16) ? 8 : 0);
    const int b_cB = (lane & 8) ? 16 : 0;

    float acc[4][8][4];
#pragma unroll
    for (int i = 0; i < 4; i++)
#pragma unroll
        for (int j = 0; j < 8; j++)
#pragma unroll
            for (int l = 0; l < 4; l++) acc[i][j][l] = 0.f;

    pf(0, 0); pf(1, 1); pf(2, 2);
    for (int c = 0; c < NC; c++) {
        int buf = c & 3;
        cp_wait<2>();
        __syncthreads();
        if (c + 3 < NC) pf(c + 3, (c + 3) & 3); else cp_commit();
        uint32_t aD = sA0 + (uint32_t)buf * 128 * G8P;
        uint32_t bD = sB0 + (uint32_t)buf * 128 * G8P;
#pragma unroll
        for (int s = 0; s < 2; s++) {
            uint32_t af[4][4];
#pragma unroll
            for (int mt = 0; mt < 4; mt++)
                ldm_x4(af[mt], aD + (uint32_t)((a_r + mt * 16) * G8P + a_cB + s * 32));
            uint32_t bfr[8][2];
#pragma unroll
            for (int np = 0; np < 4; np++) {
                uint32_t t4[4];
                ldm_x4(t4, bD + (uint32_t)((b_r + np * 16) * G8P + b_cB + s * 32));
                bfr[np * 2][0] = t4[0]; bfr[np * 2][1] = t4[1];
                bfr[np * 2 + 1][0] = t4[2]; bfr[np * 2 + 1][1] = t4[3];
            }
#pragma unroll
            for (int mt = 0; mt < 4; mt++)
#pragma unroll
                for (int nt = 0; nt < 8; nt++)
                    mma_e4(acc[mt][nt], af[mt], bfr[nt]);
        }
    }

    const int er = row0 + wm * 64 + (lane >> 2);
    const int ec = col0 + wn * 64 + (lane & 3) * 2;
#pragma unroll
    for (int mt = 0; mt < 4; mt++) {
#pragma unroll
        for (int nt = 0; nt < 8; nt++) {
            int gc = ec + nt * 8;
            float b0 = bias ? bias[gc] : 0.f;
            float b1 = bias ? bias[gc + 1] : 0.f;
#pragma unroll
            for (int half = 0; half < 2; half++) {
                int gr = er + mt * 16 + 8 * half;
                float v0 = acc[mt][nt][2 * half + 0] * WSINV + b0;
                float v1 = acc[mt][nt][2 * half + 1] * WSINV + b1;
                if (RES) {
                    float2 rr = *(const float2*)(res + (size_t)gr * N + gc);
                    v0 = rr.x + v0 * scale[gc];
                    v1 = rr.y + v1 * scale[gc + 1];
                }
                if (OHF) {
                    *(__half2*)((hf*)Cv + (size_t)gr * N + gc) =
                        __float22half2_rn(make_float2(v0, v1));
                } else {
                    *(float2*)((float*)Cv + (size_t)gr * N + gc) = make_float2(v0, v1);
                }
            }
        }
    }
}

// ---------------------------------------------------------------------------
// fp8 fused FFN up: act = relu(A @ Ww) * (A @ Wg) * WSINV^2, fp8 out
//   CTA 128x64, 8 warps (2x4), warp 64x16, K-chunk 64 bytes, 4-stage
// ---------------------------------------------------------------------------
#define FFN8_SMEM (G8STG * (128 * G8P + 64 * G8P + 64 * G8P))   // 81920 B

__global__ void __launch_bounds__(256, 2)
ffn8_dual(const f8* __restrict__ A, const f8* __restrict__ BwT,
          const f8* __restrict__ BgT, f8* __restrict__ act) {
    extern __shared__ f8 smp8[];
    const uint32_t sA0 = smem_u32(smp8);
    const uint32_t sW0 = sA0 + G8STG * 128 * G8P;
    const uint32_t sG0 = sW0 + G8STG * 64 * G8P;
    const int tid = threadIdx.x, lane = tid & 31, wid = tid >> 5;
    const int wm = wid & 1, wn = wid >> 1;
    const int row0 = blockIdx.y * 128, col0 = blockIdx.x * 64;
    const int NC = DIM >> 6;

    auto pf = [&](int c, int buf) {
        int k0 = c << 6;
        uint32_t aD = sA0 + (uint32_t)buf * 128 * G8P;
        uint32_t wD = sW0 + (uint32_t)buf * 64 * G8P;
        uint32_t gD = sG0 + (uint32_t)buf * 64 * G8P;
#pragma unroll
        for (int i = 0; i < 2; i++) {
            int idx = tid + 256 * i, r = idx >> 2, q = idx & 3;
            cp_async16(aD + (uint32_t)(r * G8P + q * 16),
                       A + (size_t)(row0 + r) * DIM + k0 + q * 16);
        }
        {
            int r = tid >> 2, q = tid & 3;
            if (r < 64) {
                cp_async16(wD + (uint32_t)(r * G8P + q * 16),
                           BwT + (size_t)(col0 + r) * DIM + k0 + q * 16);
                cp_async16(gD + (uint32_t)(r * G8P + q * 16),
                           BgT + (size_t)(col0 + r) * DIM + k0 + q * 16);
            }
        }
        cp_commit();
    };

    const int a_r = wm * 64 + (lane & 7) + ((lane & 8) ? 8 : 0);
    const int a_cB = (lane & 16) ? 16 : 0;
    const int b_r = wn * 16 + (lane & 7) + ((lane & 16) ? 8 : 0);
    const int b_cB = (lane & 8) ? 16 : 0;

    float aw[4][2][4], ag[4][2][4];
#pragma unroll
    for (int i = 0; i < 4; i++)
#pragma unroll
        for (int j = 0; j < 2; j++)
#pragma unroll
            for (int l = 0; l < 4; l++) { aw[i][j][l] = 0.f; ag[i][j][l] = 0.f; }

    pf(0, 0); pf(1, 1); pf(2, 2);
    for (int c = 0; c < NC; c++) {
        int buf = c & 3;
        cp_wait<2>();
        __syncthreads();
        if (c + 3 < NC) pf(c + 3, (c + 3) & 3); else cp_commit();
        uint32_t aD = sA0 + (uint32_t)buf * 128 * G8P;
        uint32_t wD = sW0 + (uint32_t)buf * 64 * G8P;
        uint32_t gD = sG0 + (uint32_t)buf * 64 * G8P;
#pragma unroll
        for (int s = 0; s < 2; s++) {
            uint32_t af[4][4];
#pragma unroll
            for (int mt = 0; mt < 4; mt++)
                ldm_x4(af[mt], aD + (uint32_t)((a_r + mt * 16) * G8P + a_cB + s * 32));
            uint32_t bw[2][2], bg[2][2];
            {
                uint32_t t4[4];
                ldm_x4(t4, wD + (uint32_t)(b_r * G8P + b_cB + s * 32));
                bw[0][0] = t4[0]; bw[0][1] = t4[1]; bw[1][0] = t4[2]; bw[1][1] = t4[3];
                ldm_x4(t4, gD + (uint32_t)(b_r * G8P + b_cB + s * 32));
                bg[0][0] = t4[0]; bg[0][1] = t4[1]; bg[1][0] = t4[2]; bg[1][1] = t4[3];
            }
#pragma unroll
            for (int mt = 0; mt < 4; mt++)
#pragma unroll
                for (int nt = 0; nt < 2; nt++) {
                    mma_e4(aw[mt][nt], af[mt], bw[nt]);
                    mma_e4(ag[mt][nt], af[mt], bg[nt]);
                }
        }
    }

    const int er = row0 + wm * 64 + (lane >> 2);
    const int ec = col0 + wn * 16 + (lane & 3) * 2;
    const float ws2 = WSINV * WSINV;
#pragma unroll
    for (int mt = 0; mt < 4; mt++)
#pragma unroll
        for (int nt = 0; nt < 2; nt++)
#pragma unroll
            for (int half = 0; half < 2; half++) {
                int gr = er + mt * 16 + 8 * half;
                float w0 = fmaxf(aw[mt][nt][2 * half + 0], 0.f) * ag[mt][nt][2 * half + 0] * ws2;
                float w1 = fmaxf(aw[mt][nt][2 * half + 1], 0.f) * ag[mt][nt][2 * half + 1] * ws2;
                *(unsigned short*)(act + (size_t)gr * HPAD + ec + nt * 8) =
                    f2tofp8(make_float2(w0, w1));
            }
}

// ---------------------------------------------------------------------------
// scores: attn[bh,n,d] = sum_j qi[bh,n,j] * k[bh,d,j]  -> fp8 e4m3 out
// ---------------------------------------------------------------------------
#define SP 72

__global__ void __launch_bounds__(256)
scores_mma(const hf* __restrict__ qi, const hf* __restrict__ qkv,
           f8* __restrict__ attn) {
    __shared__ hf sQ[128 * SP];
    __shared__ hf sK[128 * SP];
    const int tid = threadIdx.x, lane = tid & 31, wid = tid >> 5;
    const int wm = wid & 1, wn = wid >> 1;
    const int bh = blockIdx.z, b = bh >> 4, h = bh & 15;
    const int n0 = blockIdx.y * 128, d0 = blockIdx.x * 128;
    uint32_t sQa = smem_u32(sQ), sKa = smem_u32(sK);

#pragma unroll
    for (int i = 0; i < 4; i++) {
        int idx = tid + 256 * i, r = idx >> 3, q = idx & 7;
        cp_async16(sQa + (uint32_t)(r * SP + q * 8) * 2,
                   qi + ((size_t)bh * NSEQ + n0 + r) * HD + q * 8);
        cp_async16(sKa + (uint32_t)(r * SP + q * 8) * 2,
                   qkv + (size_t)(b * NSEQ + d0 + r) * TDIM + DIM + h * HD + q * 8);
    }
    cp_commit(); cp_wait<0>();
    __syncthreads();

    const int a_r = wm * 64 + (lane & 7) + ((lane & 8) ? 8 : 0);
    const int a_c = (lane & 16) ? 8 : 0;
    const int bn_r = wn * 32 + (lane & 7) + ((lane & 16) ? 8 : 0);
    const int bn_c = (lane & 8) ? 8 : 0;

    uint32_t acc[4][4][2];
#pragma unroll
    for (int i = 0; i < 4; i++)
#pragma unroll
        for (int j = 0; j < 4; j++) { acc[i][j][0] = 0u; acc[i][j][1] = 0u; }

#pragma unroll
    for (int s = 0; s < 4; s++) {
        uint32_t af[4][4];
#pragma unroll
        for (int mt = 0; mt < 4; mt++)
            ldm_x4(af[mt], sQa + (uint32_t)((a_r + mt * 16) * SP + a_c + s * 16) * 2);
        uint32_t bfr[4][2];
#pragma unroll
        for (int np = 0; np < 2; np++) {
            uint32_t t4[4];
            ldm_x4(t4, sKa + (uint32_t)((bn_r + np * 16) * SP + bn_c + s * 16) * 2);
            bfr[np * 2][0] = t4[0]; bfr[np * 2][1] = t4[1];
            bfr[np * 2 + 1][0] = t4[2]; bfr[np * 2 + 1][1] = t4[3];
        }
#pragma unroll
        for (int mt = 0; mt < 4; mt++)
#pragma unroll
            for (int nt = 0; nt < 4; nt++)
                mma_f16(acc[mt][nt], af[mt], bfr[nt]);
    }

    const int er = n0 + wm * 64 + (lane >> 2);
    const int ec = d0 + wn * 32 + (lane & 3) * 2;
#pragma unroll
    for (int mt = 0; mt < 4; mt++)
#pragma unroll
        for (int nt = 0; nt < 4; nt++)
#pragma unroll
            for (int half = 0; half < 2; half++) {
                int gr = er + mt * 16 + 8 * half;
                unsigned short p = f2tofp8(h2f2(acc[mt][nt][half]));
                *(unsigned short*)(attn + ((size_t)bh * NSEQ + gr) * NSEQ + ec + nt * 8) = p;
            }
}

// ---------------------------------------------------------------------------
// vt: transpose V to fp8 [bh][c][d]
// ---------------------------------------------------------------------------
__global__ void __launch_bounds__(256)
vt_conv(const hf* __restrict__ qkv, f8* __restrict__ vt) {
    __shared__ hf s[128][65];
    const int bh = blockIdx.y, b = bh >> 4, h = bh & 15;
    const int d0 = blockIdx.x * 128;
    const int t = threadIdx.x;
#pragma unroll
    for (int i = 0; i < 4; i++) {
        int idx = t + 256 * i, d = idx >> 3, q = idx & 7;
        uint4 v = *(const uint4*)(qkv + (size_t)(b * NSEQ + d0 + d) * TDIM
                                  + 2 * DIM + h * HD + q * 8);
        const hf* hp = (const hf*)&v;
#pragma unroll
        for (int j = 0; j < 8; j++) s[d][q * 8 + j] = hp[j];
    }
    __syncthreads();
#pragma unroll
    for (int i = 0; i < 2; i++) {
        int idx = t + 256 * i, c = idx >> 3, q = idx & 7;
        uint32_t u[4];
#pragma unroll
        for (int k = 0; k < 4; k++) {
            int dd = q * 16 + k * 4;
            float2 lo = make_float2(__half2float(s[dd + 0][c]), __half2float(s[dd + 1][c]));
            float2 hi = make_float2(__half2float(s[dd + 2][c]), __half2float(s[dd + 3][c]));
            u[k] = (uint32_t)f2tofp8(lo) | ((uint32_t)f2tofp8(hi) << 16);
        }
        *(uint4*)(vt + ((size_t)bh * HD + c) * NSEQ + d0 + q * 16) =
            make_uint4(u[0], u[1], u[2], u[3]);
    }
}

// ---------------------------------------------------------------------------
// o (fp8): o[b,n,h*64+c] = (1/256) * sum_d attnP256[bh,n,d] * vt[bh,c,d]
//   fp8 out (feeds proj gemm_f8)
// ---------------------------------------------------------------------------
#define OA_PITCH 80
#define OSTG 4
#define O8_SMEM (OSTG * (128 * OA_PITCH + 64 * OA_PITCH))

__global__ void __launch_bounds__(256, 2)
o_mma(const f8* __restrict__ attn, const f8* __restrict__ vt,
      f8* __restrict__ o) {
    extern __shared__ f8 smp8[];
    const uint32_t sA0 = smem_u32(smp8);
    const uint32_t sB0 = sA0 + OSTG * 128 * OA_PITCH;
    const int tid = threadIdx.x, lane = tid & 31, wid = tid >> 5;
    const int wm = wid & 3, wn = wid >> 2;
    const int bh = blockIdx.y, b = bh >> 4, h = bh & 15;
    const int n0 = blockIdx.x * 128;

    auto pf = [&](int c, int buf) {
        int k0 = c << 6;
        uint32_t aD = sA0 + (uint32_t)buf * 128 * OA_PITCH;
        uint32_t bD = sB0 + (uint32_t)buf * 64 * OA_PITCH;
#pragma unroll
        for (int i = 0; i < 2; i++) {
            int idx = tid + 256 * i, r = idx >> 2, q = idx & 3;
            cp_async16(aD + (uint32_t)(r * OA_PITCH + q * 16),
                       attn + ((size_t)bh * NSEQ + n0 + r) * NSEQ + k0 + q * 16);
        }
        {
            int r = tid >> 2, q = tid & 3;
            cp_async16(bD + (uint32_t)(r * OA_PITCH + q * 16),
                       vt + ((size_t)bh * HD + r) * NSEQ + k0 + q * 16);
        }
        cp_commit();
    };

    const int a_r = wm * 32 + (lane & 7) + ((lane & 8) ? 8 : 0);
    const int a_cB = (lane & 16) ? 16 : 0;
    const int b_r = wn * 32 + (lane & 7) + ((lane & 16) ? 8 : 0);
    const int b_cB = (lane & 8) ? 16 : 0;

    float acc[2][4][4];
#pragma unroll
    for (int i = 0; i < 2; i++)
#pragma unroll
        for (int j = 0; j < 4; j++)
#pragma unroll
            for (int l = 0; l < 4; l++) acc[i][j][l] = 0.f;

    const int NC = NSEQ / 64;
    pf(0, 0); pf(1, 1); pf(2, 2);
    for (int c = 0; c < NC; c++) {
        int buf = c & 3;
        cp_wait<2>();
        __syncthreads();
        if (c + 3 < NC) pf(c + 3, (c + 3) & 3); else cp_commit();
        uint32_t aD = sA0 + (uint32_t)buf * 128 * OA_PITCH;
        uint32_t bD = sB0 + (uint32_t)buf * 64 * OA_PITCH;
#pragma unroll
        for (int s = 0; s < 2; s++) {
            uint32_t af[2][4];
#pragma unroll
            for (int mt = 0; mt < 2; mt++)
                ldm_x4(af[mt], aD + (uint32_t)((a_r + mt * 16) * OA_PITCH + a_cB + s * 32));
            uint32_t bfr[4][2];
#pragma unroll
            for (int np = 0; np < 2; np++) {
                uint32_t t4[4];
                ldm_x4(t4, bD + (uint32_t)((b_r + np * 16) * OA_PITCH + b_cB + s * 32));
                bfr[np * 2][0] = t4[0]; bfr[np * 2][1] = t4[1];
                bfr[np * 2 + 1][0] = t4[2]; bfr[np * 2 + 1][1] = t4[3];
            }
#pragma unroll
            for (int mt = 0; mt < 2; mt++)
#pragma unroll
                for (int nt = 0; nt < 4; nt++)
                    mma_e4(acc[mt][nt], af[mt], bfr[nt]);
        }
    }

    const int er = n0 + wm * 32 + (lane >> 2);
    const int ec = h * HD + wn * 32 + (lane & 3) * 2;
#pragma unroll
    for (int mt = 0; mt < 2; mt++)
#pragma unroll
        for (int nt = 0; nt < 4; nt++)
#pragma unroll
            for (int half = 0; half < 2; half++) {
                int gr = er + mt * 16 + 8 * half;
                float v0 = acc[mt][nt][2 * half + 0] * INV_PSCALE;
                float v1 = acc[mt][nt][2 * half + 1] * INV_PSCALE;
                *(unsigned short*)(o + (size_t)(b * NSEQ + gr) * DIM + ec + nt * 8) =
                    f2tofp8(make_float2(v0, v1));
            }
}

// ---------------------------------------------------------------------------
// qi MMA: qi[bh,n,j] = sum_i (q[bh,n,i]*QSCALE) inter[h,i,j]  (K=64)
// ---------------------------------------------------------------------------
#define QP 72

__global__ void __launch_bounds__(128)
qi_mma(const hf* __restrict__ qkv, const float* __restrict__ inter,
       hf* __restrict__ qi) {
    __shared__ hf sQ[128 * QP];
    __shared__ hf sI[64 * QP];
    const int tid = threadIdx.x, lane = tid & 31, wid = tid >> 5;
    const int bh = blockIdx.y, b = bh >> 4, h = bh & 15;
    const int n0 = blockIdx.x * 128;
    uint32_t sQa = smem_u32(sQ), sIa = smem_u32(sI);

#pragma unroll
    for (int i = 0; i < 8; i++) {
        int idx = tid + 128 * i, r = idx >> 3, q = idx & 7;
        cp_async16(sQa + (uint32_t)(r * QP + q * 8) * 2,
                   qkv + (size_t)(b * NSEQ + n0 + r) * TDIM + h * HD + q * 8);
    }
    cp_commit();
    const float* I = inter + (size_t)h * HD * HD;
    for (int e = tid; e < HD * HD; e += 128)
        sI[(e >> 6) * QP + (e & 63)] = __float2half(I[e] * QSCALE);
    cp_wait<0>();
    __syncthreads();

    const int a_r = wid * 32 + (lane & 7) + ((lane & 8) ? 8 : 0);
    const int a_c = (lane & 16) ? 8 : 0;
    const int b_r = lane & 15;
    const int b_c = (lane & 16) ? 8 : 0;

    uint32_t acc[2][8][2];
#pragma unroll
    for (int i = 0; i < 2; i++)
#pragma unroll
        for (int j = 0; j < 8; j++) { acc[i][j][0] = 0u; acc[i][j][1] = 0u; }

#pragma unroll
    for (int s = 0; s < 4; s++) {
        uint32_t af[2][4];
#pragma unroll
        for (int mt = 0; mt < 2; mt++)
            ldm_x4(af[mt], sQa + (uint32_t)((a_r + mt * 16) * QP + a_c + s * 16) * 2);
        uint32_t bfr[8][2];
#pragma unroll
        for (int np = 0; np < 4; np++) {
            uint32_t t4[4];
            ldm_x4_t(t4, sIa + (uint32_t)((b_r + s * 16) * QP + np * 16 + b_c) * 2);
            bfr[np * 2][0] = t4[0]; bfr[np * 2][1] = t4[1];
            bfr[np * 2 + 1][0] = t4[2]; bfr[np * 2 + 1][1] = t4[3];
        }
#pragma unroll
        for (int mt = 0; mt < 2; mt++)
#pragma unroll
            for (int nt = 0; nt < 8; nt++)
                mma_f16(acc[mt][nt], af[mt], bfr[nt]);
    }

    const int er = n0 + wid * 32 + (lane >> 2);
    const int ec = (lane & 3) * 2;
#pragma unroll
    for (int mt = 0; mt < 2; mt++)
#pragma unroll
        for (int nt = 0; nt < 8; nt++)
#pragma unroll
            for (int half = 0; half < 2; half++) {
                int gr = er + mt * 16 + 8 * half;
                *(uint32_t*)(qi + ((size_t)bh * NSEQ + gr) * HD + ec + nt * 8) =
                    acc[mt][nt][half];
            }
}

// ---------------------------------------------------------------------------
// LayerNorm: fp32 in, fp8 out (thread t owns elems 4t..4t+3, packed store)
// ---------------------------------------------------------------------------
__global__ void ln8_kernel(const float* __restrict__ x, const float* __restrict__ g,
                           const float* __restrict__ b, f8* __restrict__ out) {
    int row = blockIdx.x;
    const float* xr = x + (size_t)row * DIM;
    f8* orow = out + (size_t)row * DIM;
    int t = threadIdx.x;
    float4 v4 = *(const float4*)(xr + 4 * t);
    float v[4] = {v4.x, v4.y, v4.z, v4.w};
    float s = v[0] + v[1] + v[2] + v[3];
    __shared__ float red[256];
    red[t] = s; __syncthreads();
    for (int off = 128; off > 0; off >>= 1) {
        if (t < off) red[t] += red[t + off];
        __syncthreads();
    }
    float mu = red[0] * (1.f / DIM);
    __syncthreads();
    float sq = 0.f;
#pragma unroll
    for (int i = 0; i < 4; i++) { float d = v[i] - mu; sq += d * d; }
    red[t] = sq; __syncthreads();
    for (int off = 128; off > 0; off >>= 1) {
        if (t < off) red[t] += red[t + off];
        __syncthreads();
    }
    float rstd = rsqrtf(red[0] * (1.f / DIM) + LN_EPS);
    float o[4];
#pragma unroll
    for (int i = 0; i < 4; i++) {
        int c = 4 * t + i;
        o[i] = (v[i] - mu) * rstd * g[c] + b[c];
    }
    uint32_t pk = (uint32_t)f2tofp8(make_float2(o[0], o[1]))
                | ((uint32_t)f2tofp8(make_float2(o[2], o[3])) << 16);
    *(uint32_t*)(orow + 4 * t) = pk;
}

// ---------------------------------------------------------------------------
// LayerNorm: fp32 in, fp16 out (for LN1 -> qi/scores path needs qkv; qkv GEMM
// consumes fp8 A, so LN1 also uses ln8. This fp16 variant unused -> removed.)
// ---------------------------------------------------------------------------

// ---------------------------------------------------------------------------
// Fused mix1 + softmax + mix2, in-place on fp8 attn (half2 math)
// ---------------------------------------------------------------------------
__global__ void __launch_bounds__(512)
midfuse_kernel(f8* __restrict__ attn,
               const float* __restrict__ plw, const float* __restrict__ plb,
               const float* __restrict__ pww, const float* __restrict__ pwb) {
    __shared__ __half2 wl2[256], ww2[256];
    __shared__ float bl[16], bw[16];
    __shared__ float red[16][17];
    __shared__ float rowmax[16], rowinv[16];
    int t = threadIdx.x;
    if (t < 256) { wl2[t] = __float2half2_rn(plw[t]); ww2[t] = __float2half2_rn(pww[t]); }
    else if (t < 272) bl[t - 256] = plb[t - 256];
    else if (t < 288) bw[t - 272] = pwb[t - 272];
    __syncthreads();

    int b = blockIdx.x >> 10, n = blockIdx.x & 1023;
    const size_t HS = (size_t)NSEQ * NSEQ;
    size_t base = ((size_t)(b * 16) * NSEQ + n) * NSEQ + (size_t)t * 2;

    __half2 s1[16];
#pragma unroll
    for (int g = 0; g < 16; g++) s1[g] = __float2half2_rn(bl[g]);
#pragma unroll
    for (int h = 0; h < 16; h++) {
        __half2 v = fp8toh2(*(const unsigned short*)(attn + base + h * HS));
#pragma unroll
        for (int g = 0; g < 16; g++)
            s1[g] = __hfma2(v, wl2[h * 16 + g], s1[g]);
    }
    int lane = t & 31, warp = t >> 5;
#pragma unroll
    for (int g = 0; g < 16; g++) {
        float2 f = __half22float2(s1[g]);
        float mm = fmaxf(f.x, f.y);
#pragma unroll
        for (int off = 16; off > 0; off >>= 1)
            mm = fmaxf(mm, __shfl_xor_sync(0xffffffffu, mm, off));
        if (lane == 0) red[g][warp] = mm;
    }
    __syncthreads();
    if (t < 16) {
        float v = red[t][0];
#pragma unroll
        for (int w2 = 1; w2 < 16; w2++) v = fmaxf(v, red[t][w2]);
        rowmax[t] = v;
    }
    __syncthreads();
#pragma unroll
    for (int g = 0; g < 16; g++) {
        float2 f = __half22float2(s1[g]);
        float mx = rowmax[g];
        float ex = __expf(f.x - mx), ey = __expf(f.y - mx);
        float ss = ex + ey;
#pragma unroll
        for (int off = 16; off > 0; off >>= 1)
            ss += __shfl_xor_sync(0xffffffffu, ss, off);
        if (lane == 0) red[g][warp] = ss;
        s1[g] = __float22half2_rn(make_float2(ex, ey));
    }
    __syncthreads();
    if (t < 16) {
        float v = 0.f;
#pragma unroll
        for (int w2 = 0; w2 < 16; w2++) v += red[t][w2];
        rowinv[t] = 1.f / v;
    }
    __syncthreads();
    __half2 o2[16];
#pragma unroll
    for (int g2 = 0; g2 < 16; g2++) o2[g2] = __float2half2_rn(bw[g2] * PSCALE);
#pragma unroll
    for (int g = 0; g < 16; g++) {
        __half2 ph = __hmul2(s1[g], __float2half2_rn(rowinv[g] * PSCALE));
#pragma unroll
        for (int g2 = 0; g2 < 16; g2++)
            o2[g2] = __hfma2(ph, ww2[g * 16 + g2], o2[g2]);
    }
#pragma unroll
    for (int g = 0; g < 16; g++)
        *(unsigned short*)(attn + base + g * HS) = h2tofp8(o2[g]);
}

// ---------------------------------------------------------------------------
// Launch
// ---------------------------------------------------------------------------
extern "C" void kernel_launch(void* const* d_in, const int* in_sizes, int n_in,
                              void* d_out, int out_size) {
    const float* x      = (const float*)d_in[0];
    const float* ln1_g  = (const float*)d_in[2];
    const float* ln1_b  = (const float*)d_in[3];
    const float* qkv_w  = (const float*)d_in[4];
    const float* qkv_b  = (const float*)d_in[5];
    const float* inter  = (const float*)d_in[6];
    const float* pl_w   = (const float*)d_in[7];
    const float* pl_b   = (const float*)d_in[8];
    const float* pw_w   = (const float*)d_in[9];
    const float* pw_b   = (const float*)d_in[10];
    const float* proj_w = (const float*)d_in[11];
    const float* proj_b = (const float*)d_in[12];
    const float* gamma1 = (const float*)d_in[13];
    const float* ln2_g  = (const float*)d_in[14];
    const float* ln2_b  = (const float*)d_in[15];
    const float* w_wide = (const float*)d_in[16];
    const float* w_gate = (const float*)d_in[17];
    const float* w_out  = (const float*)d_in[18];
    const float* gamma2 = (const float*)d_in[19];
    float* out = (float*)d_out;

    hf *qkv, *qi;
    f8 *h, *h2, *attn, *vt, *o, *act;
    f8 *wqT, *wpT, *wwT, *wgT, *woT;
    float *x1;
    cudaGetSymbolAddress((void**)&h,    g_h);
    cudaGetSymbolAddress((void**)&qkv,  g_qkv);
    cudaGetSymbolAddress((void**)&qi,   g_qi);
    cudaGetSymbolAddress((void**)&attn, g_attn);
    cudaGetSymbolAddress((void**)&vt,   g_vt);
    cudaGetSymbolAddress((void**)&o,    g_o);
    cudaGetSymbolAddress((void**)&x1,   g_x1);
    cudaGetSymbolAddress((void**)&h2,   g_h2);
    cudaGetSymbolAddress((void**)&act,  g_act);
    cudaGetSymbolAddress((void**)&wqT,  g_wqT);
    cudaGetSymbolAddress((void**)&wpT,  g_wpT);
    cudaGetSymbolAddress((void**)&wwT,  g_wwT);
    cudaGetSymbolAddress((void**)&wgT,  g_wgT);
    cudaGetSymbolAddress((void**)&woT,  g_woT);

    cudaFuncSetAttribute((const void*)gemm_f8<false, true>,
                         cudaFuncAttributeMaxDynamicSharedMemorySize, GEMM8_SMEM);
    cudaFuncSetAttribute((const void*)gemm_f8<true, false>,
                         cudaFuncAttributeMaxDynamicSharedMemorySize, GEMM8_SMEM);
    cudaFuncSetAttribute((const void*)o_mma,
                         cudaFuncAttributeMaxDynamicSharedMemorySize, O8_SMEM);
    cudaFuncSetAttribute((const void*)ffn8_dual,
                         cudaFuncAttributeMaxDynamicSharedMemorySize, FFN8_SMEM);

    // 0. weight transpose + fp8 convert (x16)
    convw_t<<<dim3(DIM / 64, TDIM / 64), 256>>>(qkv_w, wqT, DIM, TDIM, DIM, TDIM);
    convw_t<<<dim3(DIM / 64, DIM / 64), 256>>>(proj_w, wpT, DIM, DIM, DIM, DIM);
    convw_t<<<dim3(DIM / 64, HPAD / 64), 256>>>(w_wide, wwT, DIM, HIDDEN, DIM, HPAD);
    convw_t<<<dim3(DIM / 64, HPAD / 64), 256>>>(w_gate, wgT, DIM, HIDDEN, DIM, HPAD);
    convw_t<<<dim3(HPAD / 64, DIM / 64), 256>>>(w_out, woT, HIDDEN, DIM, HPAD, DIM);

    // 1. LN1 -> fp8
    ln8_kernel<<<MTOK, 256>>>(x, ln1_g, ln1_b, h);
    // 2. qkv = (h @ wq)/16 + b (fp8 MMA, fp16 out)
    gemm_f8<false, true><<<dim3(TDIM / 128, MTOK / 128), 128, GEMM8_SMEM>>>(
        h, wqT, qkv, DIM, TDIM, qkv_b, nullptr, nullptr);
    // 2b. V -> transposed fp8
    vt_conv<<<dim3(NSEQ / 128, 4 * HEADS), 256>>>(qkv, vt);
    // 3. qi = (q*scale) @ inter[h] (fp16 MMA)
    qi_mma<<<dim3(NSEQ / 128, 4 * HEADS), 128>>>(qkv, inter, qi);
    // 4. attn = qi @ k^T (fp8 out)
    scores_mma<<<dim3(NSEQ / 128, NSEQ / 128, 4 * HEADS), 256>>>(qi, qkv, attn);
    // 5-7. fused head-mix -> softmax -> head-mix
    midfuse_kernel<<<4 * NSEQ, 512>>>(attn, pl_w, pl_b, pw_w, pw_b);
    // 8. o = (attnP256 @ v) / 256 (fp8 MMA, fp8 out)
    o_mma<<<dim3(NSEQ / 128, 4 * HEADS), 256, O8_SMEM>>>(attn, vt, o);
    // 9. x1 = x + ((o @ wp)/16 + proj_b) * gamma1 (fp32 out)
    gemm_f8<true, false><<<dim3(DIM / 128, MTOK / 128), 128, GEMM8_SMEM>>>(
        o, wpT, x1, DIM, DIM, proj_b, x, gamma1);
    // 10. LN2 -> fp8
    ln8_kernel<<<MTOK, 256>>>(x1, ln2_g, ln2_b, h2);
    // 11-12. act = relu(h2 @ ww) * (h2 @ wg) / 256 (fp8 MMA, fp8 out)
    ffn8_dual<<<dim3(HPAD / 64, MTOK / 128), 256, FFN8_SMEM>>>(h2, wwT, wgT, act);
    // 13. out = x1 + ((act @ wo)/16) * gamma2 (K = 2816; pads zero)
    gemm_f8<true, false><<<dim3(DIM / 128, MTOK / 128), 128, GEMM8_SMEM>>>(
        act, woT, out, HPAD, DIM, nullptr, x1, gamma2);
}

// round 13
// speedup vs baseline: 1.1261x; 1.1261x over previous
#include <cuda_runtime.h>
#include <cuda_fp16.h>
#include <cuda_fp8.h>
#include <cstdint>
#include <cstddef>

// ---------------------------------------------------------------------------
// Problem constants
// ---------------------------------------------------------------------------
#define MTOK   4096
#define DIM    1024
#define TDIM   3072
#define HEADS  16
#define HD     64
#define HIDDEN 2730
#define HPAD   2816
#define NSEQ   1024
#define QSCALE 0.125f
#define LN_EPS 1e-6f
#define PSCALE 256.f
#define INV_PSCALE (1.f / 256.f)

typedef __half hf;
typedef unsigned char f8;

// ---------------------------------------------------------------------------
// Scratch (device globals)
// ---------------------------------------------------------------------------
__device__ hf    g_h   [MTOK * DIM];
__device__ hf    g_qkv [MTOK * TDIM];
__device__ hf    g_qi  [4 * HEADS * NSEQ * HD];
__device__ f8    g_attn[(size_t)4 * HEADS * NSEQ * NSEQ];
__device__ f8    g_vt  [(size_t)4 * HEADS * HD * NSEQ];
__device__ hf    g_o   [MTOK * DIM];
__device__ float g_x1  [MTOK * DIM];
__device__ hf    g_h2  [MTOK * DIM];
__device__ hf    g_wide[MTOK * HPAD];
// preconverted fp16 weights (padded)
__device__ hf    g_wq[DIM * TDIM];
__device__ hf    g_wp[DIM * DIM];
__device__ hf    g_ww[DIM * HPAD];
__device__ hf    g_wg[DIM * HPAD];
__device__ hf    g_wo[HPAD * DIM];

// ---------------------------------------------------------------------------
// PTX helpers
// ---------------------------------------------------------------------------
__device__ __forceinline__ uint32_t smem_u32(const void* p) {
    uint32_t a;
    asm("{ .reg .u64 t; cvta.to.shared.u64 t, %1; cvt.u32.u64 %0, t; }" : "=r"(a) : "l"(p));
    return a;
}
__device__ __forceinline__ void cp_async16(uint32_t dst, const void* src) {
    asm volatile("cp.async.cg.shared.global [%0], [%1], 16;" :: "r"(dst), "l"(src));
}
__device__ __forceinline__ void cp_commit() { asm volatile("cp.async.commit_group;"); }
template <int N> __device__ __forceinline__ void cp_wait() {
    asm volatile("cp.async.wait_group %0;" :: "n"(N));
}
__device__ __forceinline__ void ldm_x4(uint32_t* r, uint32_t a) {
    asm volatile("ldmatrix.sync.aligned.m8n8.x4.shared.b16 {%0,%1,%2,%3}, [%4];"
                 : "=r"(r[0]), "=r"(r[1]), "=r"(r[2]), "=r"(r[3]) : "r"(a));
}
__device__ __forceinline__ void ldm_x4_t(uint32_t* r, uint32_t a) {
    asm volatile("ldmatrix.sync.aligned.m8n8.x4.trans.shared.b16 {%0,%1,%2,%3}, [%4];"
                 : "=r"(r[0]), "=r"(r[1]), "=r"(r[2]), "=r"(r[3]) : "r"(a));
}
__device__ __forceinline__ void mma_f16(uint32_t* d, const uint32_t* a, const uint32_t* b) {
    asm volatile(
        "mma.sync.aligned.m16n8k16.row.col.f16.f16.f16.f16 "
        "{%0,%1},{%2,%3,%4,%5},{%6,%7},{%0,%1};"
        : "+r"(d[0]), "+r"(d[1])
        : "r"(a[0]), "r"(a[1]), "r"(a[2]), "r"(a[3]), "r"(b[0]), "r"(b[1]));
}
// fp8 e4m3 MMA, f32 accumulate (used only in o_mma)
__device__ __forceinline__ void mma_e4(float* d, const uint32_t* a, const uint32_t* b) {
    asm volatile(
        "mma.sync.aligned.m16n8k32.row.col.f32.e4m3.e4m3.f32 "
        "{%0,%1,%2,%3},{%4,%5,%6,%7},{%8,%9},{%0,%1,%2,%3};"
        : "+f"(d[0]), "+f"(d[1]), "+f"(d[2]), "+f"(d[3])
        : "r"(a[0]), "r"(a[1]), "r"(a[2]), "r"(a[3]), "r"(b[0]), "r"(b[1]));
}
__device__ __forceinline__ float2 h2f2(uint32_t u) {
    __half2 h = *reinterpret_cast<__half2*>(&u);
    return __half22float2(h);
}
__device__ __forceinline__ unsigned short f2tofp8(float2 v) {
    return __nv_cvt_float2_to_fp8x2(v, __NV_SATFINITE, __NV_E4M3);
}
__device__ __forceinline__ __half2 fp8toh2(unsigned short raw) {
    __half2_raw hr = __nv_cvt_fp8x2_to_halfraw2(raw, __NV_E4M3);
    return *reinterpret_cast<__half2*>(&hr);
}
__device__ __forceinline__ unsigned short h2tofp8(__half2 v) {
    __half2_raw hr = *reinterpret_cast<__half2_raw*>(&v);
    return __nv_cvt_halfraw2_to_fp8x2(hr, __NV_SATFINITE, __NV_E4M3);
}

// ---------------------------------------------------------------------------
// Mega weight convert: 5 weights in one launch. Segments in 8-elem units.
// ---------------------------------------------------------------------------
#define SEG0 (DIM * TDIM / 8)
#define SEG1 (SEG0 + DIM * DIM / 8)
#define SEG2 (SEG1 + DIM * HPAD / 8)
#define SEG3 (SEG2 + DIM * HPAD / 8)
#define SEG4 (SEG3 + HPAD * DIM / 8)

__global__ void convw_all(const float* __restrict__ qkv_w, const float* __restrict__ proj_w,
                          const float* __restrict__ w_wide, const float* __restrict__ w_gate,
                          const float* __restrict__ w_out,
                          hf* __restrict__ wq, hf* __restrict__ wp,
                          hf* __restrict__ ww, hf* __restrict__ wg,
                          hf* __restrict__ wo) {
    int i = blockIdx.x * 256 + threadIdx.x;
    if (i >= SEG4) return;
    const float* src; hf* dst; int C, CP, R; int base;
    if (i < SEG0)      { src = qkv_w;  dst = wq; R = DIM;    C = TDIM;   CP = TDIM; base = 0; }
    else if (i < SEG1) { src = proj_w; dst = wp; R = DIM;    C = DIM;    CP = DIM;  base = SEG0; }
    else if (i < SEG2) { src = w_wide; dst = ww; R = DIM;    C = HIDDEN; CP = HPAD; base = SEG1; }
    else if (i < SEG3) { src = w_gate; dst = wg; R = DIM;    C = HIDDEN; CP = HPAD; base = SEG2; }
    else               { src = w_out;  dst = wo; R = HIDDEN; C = DIM;    CP = DIM;  base = SEG3; }
    size_t i0 = (size_t)(i - base) * 8;
    int r = (int)(i0 / CP);
    int c = (int)(i0 - (size_t)r * CP);
    union { hf h[8]; uint4 u; } v;
    if (C == CP && r < R) {
        const float* s = src + (size_t)r * C + c;
        float4 f0 = *(const float4*)s;
        float4 f1 = *(const float4*)(s + 4);
        v.h[0] = __float2half(f0.x); v.h[1] = __float2half(f0.y);
        v.h[2] = __float2half(f0.z); v.h[3] = __float2half(f0.w);
        v.h[4] = __float2half(f1.x); v.h[5] = __float2half(f1.y);
        v.h[6] = __float2half(f1.z); v.h[7] = __float2half(f1.w);
    } else {
#pragma unroll
        for (int j = 0; j < 8; j++) {
            float f = (r < R && c + j < C) ? src[(size_t)r * C + c + j] : 0.f;
            v.h[j] = __float2half(f);
        }
    }
    *(uint4*)(dst + i0) = v.u;
}

// ---------------------------------------------------------------------------
// fp16 MMA GEMM, 3-stage cp.async, 3 CTAs/SM: C[M,N] = epi(A[M,K] @ B[K,N])
//   128x128 CTA tile, 4 warps (2x2), warp 64x64, K-chunk 32, f16 accumulate
// ---------------------------------------------------------------------------
#define AP 40
#define BP 136
#define DSTG 3
#define GEMM_SMEM (DSTG * (128 * AP + 32 * BP) * 2)

template <bool RES, bool OHF>
__global__ void __launch_bounds__(128, 3)
gemm_f16(const hf* __restrict__ A, const hf* __restrict__ B, void* __restrict__ Cv,
         int K, int N, const float* __restrict__ bias,
         const float* __restrict__ res, const float* __restrict__ scale) {
    extern __shared__ hf smp[];
    const uint32_t sA0 = smem_u32(smp);
    const uint32_t sB0 = sA0 + DSTG * 128 * AP * 2;
    const int tid = threadIdx.x, lane = tid & 31, wid = tid >> 5;
    const int wm = wid & 1, wn = wid >> 1;
    const int row0 = blockIdx.y * 128, col0 = blockIdx.x * 128;
    const int NC = K >> 5;

    auto pf = [&](int c, int buf) {
        int k0 = c << 5;
        uint32_t aD = sA0 + (uint32_t)buf * 128 * AP * 2;
        uint32_t bD = sB0 + (uint32_t)buf * 32 * BP * 2;
#pragma unroll
        for (int i = 0; i < 4; i++) {
            int idx = tid + 128 * i, r = idx >> 2, q = idx & 3;
            cp_async16(aD + (uint32_t)(r * AP + q * 8) * 2,
                       A + (size_t)(row0 + r) * K + k0 + q * 8);
        }
#pragma unroll
        for (int i = 0; i < 4; i++) {
            int idx = tid + 128 * i, r = idx >> 4, q = idx & 15;
            cp_async16(bD + (uint32_t)(r * BP + q * 8) * 2,
                       B + (size_t)(k0 + r) * N + col0 + q * 8);
        }
        cp_commit();
    };

    const int a_r = wm * 64 + (lane & 7) + ((lane & 8) ? 8 : 0);
    const int a_c = (lane & 16) ? 8 : 0;
    const int b_r = lane & 15;
    const int b_c = wn * 64 + ((lane & 16) ? 8 : 0);

    uint32_t acc[4][8][2];
#pragma unroll
    for (int i = 0; i < 4; i++)
#pragma unroll
        for (int j = 0; j < 8; j++) { acc[i][j][0] = 0u; acc[i][j][1] = 0u; }

    pf(0, 0); pf(1, 1);
    int buf = 0;
    for (int c = 0; c < NC; c++) {
        cp_wait<1>();
        __syncthreads();
        if (c + 2 < NC) {
            int nb = buf + 2; if (nb >= DSTG) nb -= DSTG;
            pf(c + 2, nb);
        } else cp_commit();
        uint32_t aD = sA0 + (uint32_t)buf * 128 * AP * 2;
        uint32_t bD = sB0 + (uint32_t)buf * 32 * BP * 2;
#pragma unroll
        for (int s = 0; s < 2; s++) {
            uint32_t af[4][4];
#pragma unroll
            for (int mt = 0; mt < 4; mt++)
                ldm_x4(af[mt], aD + (uint32_t)((a_r + mt * 16) * AP + a_c + s * 16) * 2);
            uint32_t bfr[8][2];
#pragma unroll
            for (int np = 0; np < 4; np++) {
                uint32_t t4[4];
                ldm_x4_t(t4, bD + (uint32_t)((b_r + s * 16) * BP + b_c + np * 16) * 2);
                bfr[np * 2][0] = t4[0]; bfr[np * 2][1] = t4[1];
                bfr[np * 2 + 1][0] = t4[2]; bfr[np * 2 + 1][1] = t4[3];
            }
#pragma unroll
            for (int mt = 0; mt < 4; mt++)
#pragma unroll
                for (int nt = 0; nt < 8; nt++)
                    mma_f16(acc[mt][nt], af[mt], bfr[nt]);
        }
        if (++buf >= DSTG) buf = 0;
    }

    const int er = row0 + wm * 64 + (lane >> 2);
    const int ec = col0 + wn * 64 + (lane & 3) * 2;
#pragma unroll
    for (int mt = 0; mt < 4; mt++) {
#pragma unroll
        for (int nt = 0; nt < 8; nt++) {
            int gc = ec + nt * 8;
            float b0 = bias ? bias[gc] : 0.f;
            float b1 = bias ? bias[gc + 1] : 0.f;
#pragma unroll
            for (int half = 0; half < 2; half++) {
                int gr = er + mt * 16 + 8 * half;
                float2 av = h2f2(acc[mt][nt][half]);
                float v0 = av.x + b0, v1 = av.y + b1;
                if (RES) {
                    float2 rr = *(const float2*)(res + (size_t)gr * N + gc);
                    v0 = rr.x + v0 * scale[gc];
                    v1 = rr.y + v1 * scale[gc + 1];
                }
                if (OHF) {
                    *(__half2*)((hf*)Cv + (size_t)gr * N + gc) =
                        __float22half2_rn(make_float2(v0, v1));
                } else {
                    *(float2*)((float*)Cv + (size_t)gr * N + gc) = make_float2(v0, v1);
                }
            }
        }
    }
}

// ---------------------------------------------------------------------------
// Fused FFN up v2: act = relu(A @ Ww) * (A @ Wg), fp16 out, f16 acc
//   CTA 128x64, 4 warps (2x2), warp 64x32 per operand, 3-stage, 3 CTAs/SM
// ---------------------------------------------------------------------------
#define FBP 72
#define FFN_SMEM (DSTG * (128 * AP + 2 * 32 * FBP) * 2)   // 58368 B

__global__ void __launch_bounds__(128, 3)
ffn_dual(const hf* __restrict__ A, const hf* __restrict__ Bw,
         const hf* __restrict__ Bg, hf* __restrict__ act) {
    extern __shared__ hf smp[];
    const uint32_t sA0 = smem_u32(smp);
    const uint32_t sW0 = sA0 + DSTG * 128 * AP * 2;
    const uint32_t sG0 = sW0 + DSTG * 32 * FBP * 2;
    const int tid = threadIdx.x, lane = tid & 31, wid = tid >> 5;
    const int wm = wid & 1, wn = wid >> 1;
    const int row0 = blockIdx.y * 128, col0 = blockIdx.x * 64;
    const int NC = DIM >> 5;

    auto pf = [&](int c, int buf) {
        int k0 = c << 5;
        uint32_t aD = sA0 + (uint32_t)buf * 128 * AP * 2;
        uint32_t wD = sW0 + (uint32_t)buf * 32 * FBP * 2;
        uint32_t gD = sG0 + (uint32_t)buf * 32 * FBP * 2;
#pragma unroll
        for (int i = 0; i < 4; i++) {
            int idx = tid + 128 * i, r = idx >> 2, q = idx & 3;
            cp_async16(aD + (uint32_t)(r * AP + q * 8) * 2,
                       A + (size_t)(row0 + r) * DIM + k0 + q * 8);
        }
#pragma unroll
        for (int i = 0; i < 2; i++) {
            int idx = tid + 128 * i, r = idx >> 3, q = idx & 7;
            cp_async16(wD + (uint32_t)(r * FBP + q * 8) * 2,
                       Bw + (size_t)(k0 + r) * HPAD + col0 + q * 8);
            cp_async16(gD + (uint32_t)(r * FBP + q * 8) * 2,
                       Bg + (size_t)(k0 + r) * HPAD + col0 + q * 8);
        }
        cp_commit();
    };

    const int a_r = wm * 64 + (lane & 7) + ((lane & 8) ? 8 : 0);
    const int a_c = (lane & 16) ? 8 : 0;
    const int b_r = lane & 15;
    const int b_c = wn * 32 + ((lane & 16) ? 8 : 0);

    uint32_t aw[4][4][2], ag[4][4][2];
#pragma unroll
    for (int i = 0; i < 4; i++)
#pragma unroll
        for (int j = 0; j < 4; j++) {
            aw[i][j][0] = aw[i][j][1] = 0u;
            ag[i][j][0] = ag[i][j][1] = 0u;
        }

    pf(0, 0); pf(1, 1);
    int buf = 0;
    for (int c = 0; c < NC; c++) {
        cp_wait<1>();
        __syncthreads();
        if (c + 2 < NC) {
            int nb = buf + 2; if (nb >= DSTG) nb -= DSTG;
            pf(c + 2, nb);
        } else cp_commit();
        uint32_t aD = sA0 + (uint32_t)buf * 128 * AP * 2;
        uint32_t wD = sW0 + (uint32_t)buf * 32 * FBP * 2;
        uint32_t gD = sG0 + (uint32_t)buf * 32 * FBP * 2;
#pragma unroll
        for (int s = 0; s < 2; s++) {
            uint32_t af[4][4];
#pragma unroll
            for (int mt = 0; mt < 4; mt++)
                ldm_x4(af[mt], aD + (uint32_t)((a_r + mt * 16) * AP + a_c + s * 16) * 2);
            uint32_t bw[4][2], bg[4][2];
#pragma unroll
            for (int np = 0; np < 2; np++) {
                uint32_t t4[4];
                ldm_x4_t(t4, wD + (uint32_t)((b_r + s * 16) * FBP + b_c + np * 16) * 2);
                bw[np * 2][0] = t4[0]; bw[np * 2][1] = t4[1];
                bw[np * 2 + 1][0] = t4[2]; bw[np * 2 + 1][1] = t4[3];
                ldm_x4_t(t4, gD + (uint32_t)((b_r + s * 16) * FBP + b_c + np * 16) * 2);
                bg[np * 2][0] = t4[0]; bg[np * 2][1] = t4[1];
                bg[np * 2 + 1][0] = t4[2]; bg[np * 2 + 1][1] = t4[3];
            }
#pragma unroll
            for (int mt = 0; mt < 4; mt++)
#pragma unroll
                for (int nt = 0; nt < 4; nt++) {
                    mma_f16(aw[mt][nt], af[mt], bw[nt]);
                    mma_f16(ag[mt][nt], af[mt], bg[nt]);
                }
        }
        if (++buf >= DSTG) buf = 0;
    }

    const int er = row0 + wm * 64 + (lane >> 2);
    const int ec = col0 + wn * 32 + (lane & 3) * 2;
#pragma unroll
    for (int mt = 0; mt < 4; mt++)
#pragma unroll
        for (int nt = 0; nt < 4; nt++)
#pragma unroll
            for (int half = 0; half < 2; half++) {
                int gr = er + mt * 16 + 8 * half;
                float2 fw = h2f2(aw[mt][nt][half]);
                float2 fg = h2f2(ag[mt][nt][half]);
                float w0 = fmaxf(fw.x, 0.f) * fg.x;
                float w1 = fmaxf(fw.y, 0.f) * fg.y;
                *(__half2*)(act + (size_t)gr * HPAD + ec + nt * 8) =
                    __float22half2_rn(make_float2(w0, w1));
            }
}

// ---------------------------------------------------------------------------
// scores: attn[bh,n,d] = sum_j qi[bh,n,j] * k[bh,d,j]  -> fp8 e4m3 out
// ---------------------------------------------------------------------------
#define SP 72

__global__ void __launch_bounds__(256)
scores_mma(const hf* __restrict__ qi, const hf* __restrict__ qkv,
           f8* __restrict__ attn) {
    __shared__ hf sQ[128 * SP];
    __shared__ hf sK[128 * SP];
    const int tid = threadIdx.x, lane = tid & 31, wid = tid >> 5;
    const int wm = wid & 1, wn = wid >> 1;
    const int bh = blockIdx.z, b = bh >> 4, h = bh & 15;
    const int n0 = blockIdx.y * 128, d0 = blockIdx.x * 128;
    uint32_t sQa = smem_u32(sQ), sKa = smem_u32(sK);

#pragma unroll
    for (int i = 0; i < 4; i++) {
        int idx = tid + 256 * i, r = idx >> 3, q = idx & 7;
        cp_async16(sQa + (uint32_t)(r * SP + q * 8) * 2,
                   qi + ((size_t)bh * NSEQ + n0 + r) * HD + q * 8);
        cp_async16(sKa + (uint32_t)(r * SP + q * 8) * 2,
                   qkv + (size_t)(b * NSEQ + d0 + r) * TDIM + DIM + h * HD + q * 8);
    }
    cp_commit(); cp_wait<0>();
    __syncthreads();

    const int a_r = wm * 64 + (lane & 7) + ((lane & 8) ? 8 : 0);
    const int a_c = (lane & 16) ? 8 : 0;
    const int bn_r = wn * 32 + (lane & 7) + ((lane & 16) ? 8 : 0);
    const int bn_c = (lane & 8) ? 8 : 0;

    uint32_t acc[4][4][2];
#pragma unroll
    for (int i = 0; i < 4; i++)
#pragma unroll
        for (int j = 0; j < 4; j++) { acc[i][j][0] = 0u; acc[i][j][1] = 0u; }

#pragma unroll
    for (int s = 0; s < 4; s++) {
        uint32_t af[4][4];
#pragma unroll
        for (int mt = 0; mt < 4; mt++)
            ldm_x4(af[mt], sQa + (uint32_t)((a_r + mt * 16) * SP + a_c + s * 16) * 2);
        uint32_t bfr[4][2];
#pragma unroll
        for (int np = 0; np < 2; np++) {
            uint32_t t4[4];
            ldm_x4(t4, sKa + (uint32_t)((bn_r + np * 16) * SP + bn_c + s * 16) * 2);
            bfr[np * 2][0] = t4[0]; bfr[np * 2][1] = t4[1];
            bfr[np * 2 + 1][0] = t4[2]; bfr[np * 2 + 1][1] = t4[3];
        }
#pragma unroll
        for (int mt = 0; mt < 4; mt++)
#pragma unroll
            for (int nt = 0; nt < 4; nt++)
                mma_f16(acc[mt][nt], af[mt], bfr[nt]);
    }

    const int er = n0 + wm * 64 + (lane >> 2);
    const int ec = d0 + wn * 32 + (lane & 3) * 2;
#pragma unroll
    for (int mt = 0; mt < 4; mt++)
#pragma unroll
        for (int nt = 0; nt < 4; nt++)
#pragma unroll
            for (int half = 0; half < 2; half++) {
                int gr = er + mt * 16 + 8 * half;
                unsigned short p = f2tofp8(h2f2(acc[mt][nt][half]));
                *(unsigned short*)(attn + ((size_t)bh * NSEQ + gr) * NSEQ + ec + nt * 8) = p;
            }
}

// ---------------------------------------------------------------------------
// vt: transpose V to fp8 [bh][c][d]
// ---------------------------------------------------------------------------
__global__ void __launch_bounds__(256)
vt_conv(const hf* __restrict__ qkv, f8* __restrict__ vt) {
    __shared__ hf s[128][65];
    const int bh = blockIdx.y, b = bh >> 4, h = bh & 15;
    const int d0 = blockIdx.x * 128;
    const int t = threadIdx.x;
#pragma unroll
    for (int i = 0; i < 4; i++) {
        int idx = t + 256 * i, d = idx >> 3, q = idx & 7;
        uint4 v = *(const uint4*)(qkv + (size_t)(b * NSEQ + d0 + d) * TDIM
                                  + 2 * DIM + h * HD + q * 8);
        const hf* hp = (const hf*)&v;
#pragma unroll
        for (int j = 0; j < 8; j++) s[d][q * 8 + j] = hp[j];
    }
    __syncthreads();
#pragma unroll
    for (int i = 0; i < 2; i++) {
        int idx = t + 256 * i, c = idx >> 3, q = idx & 7;
        uint32_t u[4];
#pragma unroll
        for (int k = 0; k < 4; k++) {
            int dd = q * 16 + k * 4;
            float2 lo = make_float2(__half2float(s[dd + 0][c]), __half2float(s[dd + 1][c]));
            float2 hi = make_float2(__half2float(s[dd + 2][c]), __half2float(s[dd + 3][c]));
            u[k] = (uint32_t)f2tofp8(lo) | ((uint32_t)f2tofp8(hi) << 16);
        }
        *(uint4*)(vt + ((size_t)bh * HD + c) * NSEQ + d0 + q * 16) =
            make_uint4(u[0], u[1], u[2], u[3]);
    }
}

// ---------------------------------------------------------------------------
// o (fp8): o[b,n,h*64+c] = (1/256) * sum_d attnP256[bh,n,d] * vt[bh,c,d]
// ---------------------------------------------------------------------------
#define OA_PITCH 80
#define OSTG 4
#define O8_SMEM (OSTG * (128 * OA_PITCH + 64 * OA_PITCH))

__global__ void __launch_bounds__(256, 2)
o_mma(const f8* __restrict__ attn, const f8* __restrict__ vt,
      hf* __restrict__ o) {
    extern __shared__ f8 smp8[];
    const uint32_t sA0 = smem_u32(smp8);
    const uint32_t sB0 = sA0 + OSTG * 128 * OA_PITCH;
    const int tid = threadIdx.x, lane = tid & 31, wid = tid >> 5;
    const int wm = wid & 3, wn = wid >> 2;
    const int bh = blockIdx.y, b = bh >> 4, h = bh & 15;
    const int n0 = blockIdx.x * 128;

    auto pf = [&](int c, int buf) {
        int k0 = c << 6;
        uint32_t aD = sA0 + (uint32_t)buf * 128 * OA_PITCH;
        uint32_t bD = sB0 + (uint32_t)buf * 64 * OA_PITCH;
#pragma unroll
        for (int i = 0; i < 2; i++) {
            int idx = tid + 256 * i, r = idx >> 2, q = idx & 3;
            cp_async16(aD + (uint32_t)(r * OA_PITCH + q * 16),
                       attn + ((size_t)bh * NSEQ + n0 + r) * NSEQ + k0 + q * 16);
        }
        {
            int r = tid >> 2, q = tid & 3;
            cp_async16(bD + (uint32_t)(r * OA_PITCH + q * 16),
                       vt + ((size_t)bh * HD + r) * NSEQ + k0 + q * 16);
        }
        cp_commit();
    };

    const int a_r = wm * 32 + (lane & 7) + ((lane & 8) ? 8 : 0);
    const int a_cB = (lane & 16) ? 16 : 0;
    const int b_r = wn * 32 + (lane & 7) + ((lane & 16) ? 8 : 0);
    const int b_cB = (lane & 8) ? 16 : 0;

    float acc[2][4][4];
#pragma unroll
    for (int i = 0; i < 2; i++)
#pragma unroll
        for (int j = 0; j < 4; j++)
#pragma unroll
            for (int l = 0; l < 4; l++) acc[i][j][l] = 0.f;

    const int NC = NSEQ / 64;
    pf(0, 0); pf(1, 1); pf(2, 2);
    for (int c = 0; c < NC; c++) {
        int buf = c & 3;
        cp_wait<2>();
        __syncthreads();
        if (c + 3 < NC) pf(c + 3, (c + 3) & 3); else cp_commit();
        uint32_t aD = sA0 + (uint32_t)buf * 128 * OA_PITCH;
        uint32_t bD = sB0 + (uint32_t)buf * 64 * OA_PITCH;
#pragma unroll
        for (int s = 0; s < 2; s++) {
            uint32_t af[2][4];
#pragma unroll
            for (int mt = 0; mt < 2; mt++)
                ldm_x4(af[mt], aD + (uint32_t)((a_r + mt * 16) * OA_PITCH + a_cB + s * 32));
            uint32_t bfr[4][2];
#pragma unroll
            for (int np = 0; np < 2; np++) {
                uint32_t t4[4];
                ldm_x4(t4, bD + (uint32_t)((b_r + np * 16) * OA_PITCH + b_cB + s * 32));
                bfr[np * 2][0] = t4[0]; bfr[np * 2][1] = t4[1];
                bfr[np * 2 + 1][0] = t4[2]; bfr[np * 2 + 1][1] = t4[3];
            }
#pragma unroll
            for (int mt = 0; mt < 2; mt++)
#pragma unroll
                for (int nt = 0; nt < 4; nt++)
                    mma_e4(acc[mt][nt], af[mt], bfr[nt]);
        }
    }

    const int er = n0 + wm * 32 + (lane >> 2);
    const int ec = h * HD + wn * 32 + (lane & 3) * 2;
#pragma unroll
    for (int mt = 0; mt < 2; mt++)
#pragma unroll
        for (int nt = 0; nt < 4; nt++)
#pragma unroll
            for (int half = 0; half < 2; half++) {
                int gr = er + mt * 16 + 8 * half;
                float v0 = acc[mt][nt][2 * half + 0] * INV_PSCALE;
                float v1 = acc[mt][nt][2 * half + 1] * INV_PSCALE;
                *(__half2*)(o + (size_t)(b * NSEQ + gr) * DIM + ec + nt * 8) =
                    __float22half2_rn(make_float2(v0, v1));
            }
}

// ---------------------------------------------------------------------------
// qi MMA: qi[bh,n,j] = sum_i (q[bh,n,i]*QSCALE) inter[h,i,j]  (K=64)
// ---------------------------------------------------------------------------
#define QP 72

__global__ void __launch_bounds__(128)
qi_mma(const hf* __restrict__ qkv, const float* __restrict__ inter,
       hf* __restrict__ qi) {
    __shared__ hf sQ[128 * QP];
    __shared__ hf sI[64 * QP];
    const int tid = threadIdx.x, lane = tid & 31, wid = tid >> 5;
    const int bh = blockIdx.y, b = bh >> 4, h = bh & 15;
    const int n0 = blockIdx.x * 128;
    uint32_t sQa = smem_u32(sQ), sIa = smem_u32(sI);

#pragma unroll
    for (int i = 0; i < 8; i++) {
        int idx = tid + 128 * i, r = idx >> 3, q = idx & 7;
        cp_async16(sQa + (uint32_t)(r * QP + q * 8) * 2,
                   qkv + (size_t)(b * NSEQ + n0 + r) * TDIM + h * HD + q * 8);
    }
    cp_commit();
    const float* I = inter + (size_t)h * HD * HD;
    for (int e = tid; e < HD * HD; e += 128)
        sI[(e >> 6) * QP + (e & 63)] = __float2half(I[e] * QSCALE);
    cp_wait<0>();
    __syncthreads();

    const int a_r = wid * 32 + (lane & 7) + ((lane & 8) ? 8 : 0);
    const int a_c = (lane & 16) ? 8 : 0;
    const int b_r = lane & 15;
    const int b_c = (lane & 16) ? 8 : 0;

    uint32_t acc[2][8][2];
#pragma unroll
    for (int i = 0; i < 2; i++)
#pragma unroll
        for (int j = 0; j < 8; j++) { acc[i][j][0] = 0u; acc[i][j][1] = 0u; }

#pragma unroll
    for (int s = 0; s < 4; s++) {
        uint32_t af[2][4];
#pragma unroll
        for (int mt = 0; mt < 2; mt++)
            ldm_x4(af[mt], sQa + (uint32_t)((a_r + mt * 16) * QP + a_c + s * 16) * 2);
        uint32_t bfr[8][2];
#pragma unroll
        for (int np = 0; np < 4; np++) {
            uint32_t t4[4];
            ldm_x4_t(t4, sIa + (uint32_t)((b_r + s * 16) * QP + np * 16 + b_c) * 2);
            bfr[np * 2][0] = t4[0]; bfr[np * 2][1] = t4[1];
            bfr[np * 2 + 1][0] = t4[2]; bfr[np * 2 + 1][1] = t4[3];
        }
#pragma unroll
        for (int mt = 0; mt < 2; mt++)
#pragma unroll
            for (int nt = 0; nt < 8; nt++)
                mma_f16(acc[mt][nt], af[mt], bfr[nt]);
    }

    const int er = n0 + wid * 32 + (lane >> 2);
    const int ec = (lane & 3) * 2;
#pragma unroll
    for (int mt = 0; mt < 2; mt++)
#pragma unroll
        for (int nt = 0; nt < 8; nt++)
#pragma unroll
            for (int half = 0; half < 2; half++) {
                int gr = er + mt * 16 + 8 * half;
                *(uint32_t*)(qi + ((size_t)bh * NSEQ + gr) * HD + ec + nt * 8) =
                    acc[mt][nt][half];
            }
}

// ---------------------------------------------------------------------------
// LayerNorm: fp32 in, fp16 out
// ---------------------------------------------------------------------------
__global__ void ln_kernel(const float* __restrict__ x, const float* __restrict__ g,
                          const float* __restrict__ b, hf* __restrict__ out) {
    int row = blockIdx.x;
    const float* xr = x + (size_t)row * DIM;
    hf* orow = out + (size_t)row * DIM;
    int t = threadIdx.x;
    float v[4];
    float s = 0.f;
#pragma unroll
    for (int i = 0; i < 4; i++) { v[i] = xr[t + 256 * i]; s += v[i]; }
    __shared__ float red[256];
    red[t] = s; __syncthreads();
    for (int off = 128; off > 0; off >>= 1) {
        if (t < off) red[t] += red[t + off];
        __syncthreads();
    }
    float mu = red[0] * (1.f / DIM);
    __syncthreads();
    float sq = 0.f;
#pragma unroll
    for (int i = 0; i < 4; i++) { float d = v[i] - mu; sq += d * d; }
    red[t] = sq; __syncthreads();
    for (int off = 128; off > 0; off >>= 1) {
        if (t < off) red[t] += red[t + off];
        __syncthreads();
    }
    float rstd = rsqrtf(red[0] * (1.f / DIM) + LN_EPS);
#pragma unroll
    for (int i = 0; i < 4; i++) {
        int c = t + 256 * i;
        orow[c] = __float2half((v[i] - mu) * rstd * g[c] + b[c]);
    }
}

// ---------------------------------------------------------------------------
// Fused mix1 + softmax + mix2, in-place on fp8 attn (half2 math)
// ---------------------------------------------------------------------------
__global__ void __launch_bounds__(512)
midfuse_kernel(f8* __restrict__ attn,
               const float* __restrict__ plw, const float* __restrict__ plb,
               const float* __restrict__ pww, const float* __restrict__ pwb) {
    __shared__ __half2 wl2[256], ww2[256];
    __shared__ float bl[16], bw[16];
    __shared__ float red[16][17];
    __shared__ float rowmax[16], rowinv[16];
    int t = threadIdx.x;
    if (t < 256) { wl2[t] = __float2half2_rn(plw[t]); ww2[t] = __float2half2_rn(pww[t]); }
    else if (t < 272) bl[t - 256] = plb[t - 256];
    else if (t < 288) bw[t - 272] = pwb[t - 272];
    __syncthreads();

    int b = blockIdx.x >> 10, n = blockIdx.x & 1023;
    const size_t HS = (size_t)NSEQ * NSEQ;
    size_t base = ((size_t)(b * 16) * NSEQ + n) * NSEQ + (size_t)t * 2;

    __half2 s1[16];
#pragma unroll
    for (int g = 0; g < 16; g++) s1[g] = __float2half2_rn(bl[g]);
#pragma unroll
    for (int h = 0; h < 16; h++) {
        __half2 v = fp8toh2(*(const unsigned short*)(attn + base + h * HS));
#pragma unroll
        for (int g = 0; g < 16; g++)
            s1[g] = __hfma2(v, wl2[h * 16 + g], s1[g]);
    }
    int lane = t & 31, warp = t >> 5;
#pragma unroll
    for (int g = 0; g < 16; g++) {
        float2 f = __half22float2(s1[g]);
        float mm = fmaxf(f.x, f.y);
#pragma unroll
        for (int off = 16; off > 0; off >>= 1)
            mm = fmaxf(mm, __shfl_xor_sync(0xffffffffu, mm, off));
        if (lane == 0) red[g][warp] = mm;
    }
    __syncthreads();
    if (t < 16) {
        float v = red[t][0];
#pragma unroll
        for (int w2 = 1; w2 < 16; w2++) v = fmaxf(v, red[t][w2]);
        rowmax[t] = v;
    }
    __syncthreads();
#pragma unroll
    for (int g = 0; g < 16; g++) {
        float2 f = __half22float2(s1[g]);
        float mx = rowmax[g];
        float ex = __expf(f.x - mx), ey = __expf(f.y - mx);
        float ss = ex + ey;
#pragma unroll
        for (int off = 16; off > 0; off >>= 1)
            ss += __shfl_xor_sync(0xffffffffu, ss, off);
        if (lane == 0) red[g][warp] = ss;
        s1[g] = __float22half2_rn(make_float2(ex, ey));
    }
    __syncthreads();
    if (t < 16) {
        float v = 0.f;
#pragma unroll
        for (int w2 = 0; w2 < 16; w2++) v += red[t][w2];
        rowinv[t] = 1.f / v;
    }
    __syncthreads();
    __half2 o2[16];
#pragma unroll
    for (int g2 = 0; g2 < 16; g2++) o2[g2] = __float2half2_rn(bw[g2] * PSCALE);
#pragma unroll
    for (int g = 0; g < 16; g++) {
        __half2 ph = __hmul2(s1[g], __float2half2_rn(rowinv[g] * PSCALE));
#pragma unroll
        for (int g2 = 0; g2 < 16; g2++)
            o2[g2] = __hfma2(ph, ww2[g * 16 + g2], o2[g2]);
    }
#pragma unroll
    for (int g = 0; g < 16; g++)
        *(unsigned short*)(attn + base + g * HS) = h2tofp8(o2[g]);
}

// ---------------------------------------------------------------------------
// Launch
// ---------------------------------------------------------------------------
extern "C" void kernel_launch(void* const* d_in, const int* in_sizes, int n_in,
                              void* d_out, int out_size) {
    const float* x      = (const float*)d_in[0];
    const float* ln1_g  = (const float*)d_in[2];
    const float* ln1_b  = (const float*)d_in[3];
    const float* qkv_w  = (const float*)d_in[4];
    const float* qkv_b  = (const float*)d_in[5];
    const float* inter  = (const float*)d_in[6];
    const float* pl_w   = (const float*)d_in[7];
    const float* pl_b   = (const float*)d_in[8];
    const float* pw_w   = (const float*)d_in[9];
    const float* pw_b   = (const float*)d_in[10];
    const float* proj_w = (const float*)d_in[11];
    const float* proj_b = (const float*)d_in[12];
    const float* gamma1 = (const float*)d_in[13];
    const float* ln2_g  = (const float*)d_in[14];
    const float* ln2_b  = (const float*)d_in[15];
    const float* w_wide = (const float*)d_in[16];
    const float* w_gate = (const float*)d_in[17];
    const float* w_out  = (const float*)d_in[18];
    const float* gamma2 = (const float*)d_in[19];
    float* out = (float*)d_out;

    hf *h, *qkv, *qi, *o, *h2, *wide;
    hf *wq, *wp, *ww, *wg, *wo;
    f8 *attn, *vt;
    float *x1;
    cudaGetSymbolAddress((void**)&h,    g_h);
    cudaGetSymbolAddress((void**)&qkv,  g_qkv);
    cudaGetSymbolAddress((void**)&qi,   g_qi);
    cudaGetSymbolAddress((void**)&attn, g_attn);
    cudaGetSymbolAddress((void**)&vt,   g_vt);
    cudaGetSymbolAddress((void**)&o,    g_o);
    cudaGetSymbolAddress((void**)&x1,   g_x1);
    cudaGetSymbolAddress((void**)&h2,   g_h2);
    cudaGetSymbolAddress((void**)&wide, g_wide);
    cudaGetSymbolAddress((void**)&wq,   g_wq);
    cudaGetSymbolAddress((void**)&wp,   g_wp);
    cudaGetSymbolAddress((void**)&ww,   g_ww);
    cudaGetSymbolAddress((void**)&wg,   g_wg);
    cudaGetSymbolAddress((void**)&wo,   g_wo);

    cudaFuncSetAttribute((const void*)gemm_f16<false, true>,
                         cudaFuncAttributeMaxDynamicSharedMemorySize, GEMM_SMEM);
    cudaFuncSetAttribute((const void*)gemm_f16<true, false>,
                         cudaFuncAttributeMaxDynamicSharedMemorySize, GEMM_SMEM);
    cudaFuncSetAttribute((const void*)o_mma,
                         cudaFuncAttributeMaxDynamicSharedMemorySize, O8_SMEM);
    cudaFuncSetAttribute((const void*)ffn_dual,
                         cudaFuncAttributeMaxDynamicSharedMemorySize, FFN_SMEM);

    // 0. weight preconversion, single launch
    convw_all<<<(SEG4 + 255) / 256, 256>>>(qkv_w, proj_w, w_wide, w_gate, w_out,
                                           wq, wp, ww, wg, wo);

    // 1. LN1 -> fp16
    ln_kernel<<<MTOK, 256>>>(x, ln1_g, ln1_b, h);
    // 2. qkv = h @ wq + b (fp16 out)
    gemm_f16<false, true><<<dim3(TDIM / 128, MTOK / 128), 128, GEMM_SMEM>>>(
        h, wq, qkv, DIM, TDIM, qkv_b, nullptr, nullptr);
    // 2b. V -> transposed fp8
    vt_conv<<<dim3(NSEQ / 128, 4 * HEADS), 256>>>(qkv, vt);
    // 3. qi = (q*scale) @ inter[h] (fp16 MMA)
    qi_mma<<<dim3(NSEQ / 128, 4 * HEADS), 128>>>(qkv, inter, qi);
    // 4. attn = qi @ k^T (fp8 out)
    scores_mma<<<dim3(NSEQ / 128, NSEQ / 128, 4 * HEADS), 256>>>(qi, qkv, attn);
    // 5-7. fused head-mix -> softmax -> head-mix (fp8 in/out, half2 math, P*256)
    midfuse_kernel<<<4 * NSEQ, 512>>>(attn, pl_w, pl_b, pw_w, pw_b);
    // 8. o = (attnP256 @ v) / 256 (fp8 MMA, fp16 out)
    o_mma<<<dim3(NSEQ / 128, 4 * HEADS), 256, O8_SMEM>>>(attn, vt, o);
    // 9. x1 = x + (o @ wp + proj_b) * gamma1 (fp32 out)
    gemm_f16<true, false><<<dim3(DIM / 128, MTOK / 128), 128, GEMM_SMEM>>>(
        o, wp, x1, DIM, DIM, proj_b, x, gamma1);
    // 10. LN2 -> fp16
    ln_kernel<<<MTOK, 256>>>(x1, ln2_g, ln2_b, h2);
    // 11-12. act = relu(h2 @ ww) * (h2 @ wg)  (fused v2: 4 warps, 64x32, 3 CTA/SM)
    ffn_dual<<<dim3(HPAD / 64, MTOK / 128), 128, FFN_SMEM>>>(h2, ww, wg, wide);
    // 13. out = x1 + (act @ wo) * gamma2 (K = 2816; pad rows of wo are zero)
    gemm_f16<true, false><<<dim3(DIM / 128, MTOK / 128), 128, GEMM_SMEM>>>(
        wide, wo, out, HPAD, DIM, nullptr, x1, gamma2);
}